// round 1
// baseline (speedup 1.0000x reference)
#include <cuda_runtime.h>

#define TK_D       16384
#define TK_THREADS 512
#define TK_CHUNK   (TK_THREADS * 4)      // 2048 elements per chunk iteration
#define TK_NCHUNK  (TK_D / TK_CHUNK)     // 8
#define TK_CAP     2048

struct TKShared {
    unsigned long long cand[TK_CAP];   // (ordered_key << 32) | (D-1-idx)
    int cnt;
    int red;
};

// Order-preserving float->uint key: larger float <=> larger key.
__device__ __forceinline__ unsigned f2k(float f) {
    unsigned b = __float_as_uint(f);
    return b ^ ((unsigned)((int)b >> 31) | 0x80000000u);
}
__device__ __forceinline__ float k2f(unsigned u) {
    unsigned b = u ^ ((u & 0x80000000u) ? 0x80000000u : 0xFFFFFFFFu);
    return __uint_as_float(b);
}

__device__ __forceinline__ void tk_push(TKShared* sm, unsigned u, int idx) {
    int p = atomicAdd(&sm->cnt, 1);
    if (p < TK_CAP)
        sm->cand[p] = ((unsigned long long)u << 32) | (unsigned)(TK_D - 1 - idx);
}

// Stream the row once. Push elements whose key is in (tk_lo, tk_hi].
// ZERO_OUT: also write zeros to the whole output row (bulk stores, no deps).
template<bool ZERO_OUT, bool HAS_HI>
__device__ void tk_scan(const float* __restrict__ rp, float* __restrict__ op,
                        unsigned tk_lo, unsigned tk_hi, TKShared* sm, int tid) {
    #pragma unroll
    for (int c = 0; c < TK_NCHUNK; c++) {
        int base = c * TK_CHUNK + tid * 4;
        float4 v = *(const float4*)(rp + base);
        if (ZERO_OUT) {
            *(float4*)(op + base) = make_float4(0.f, 0.f, 0.f, 0.f);
        }
        unsigned u0 = f2k(v.x), u1 = f2k(v.y), u2 = f2k(v.z), u3 = f2k(v.w);
        bool h0 = (u0 > tk_lo), h1 = (u1 > tk_lo), h2 = (u2 > tk_lo), h3 = (u3 > tk_lo);
        if (HAS_HI) {
            h0 = h0 && (u0 <= tk_hi); h1 = h1 && (u1 <= tk_hi);
            h2 = h2 && (u2 <= tk_hi); h3 = h3 && (u3 <= tk_hi);
        }
        if (h0 | h1 | h2 | h3) {          // rare (~1% of elements hit)
            if (h0) tk_push(sm, u0, base + 0);
            if (h1) tk_push(sm, u1, base + 1);
            if (h2) tk_push(sm, u2, base + 2);
            if (h3) tk_push(sm, u3, base + 3);
        }
    }
}

// mode 0: count keys > a ; mode 1: count (key == a && idx <= b). Block-wide.
__device__ int tk_count(const float* __restrict__ rp, unsigned a, int b, int mode,
                        TKShared* sm, int tid) {
    __syncthreads();
    if (tid == 0) sm->red = 0;
    __syncthreads();
    int c = 0;
    #pragma unroll
    for (int ch = 0; ch < TK_NCHUNK; ch++) {
        int base = ch * TK_CHUNK + tid * 4;
        float4 v = *(const float4*)(rp + base);
        unsigned u0 = f2k(v.x), u1 = f2k(v.y), u2 = f2k(v.z), u3 = f2k(v.w);
        if (mode == 0) {
            c += (int)(u0 > a) + (int)(u1 > a) + (int)(u2 > a) + (int)(u3 > a);
        } else {
            c += (int)(u0 == a && base + 0 <= b) + (int)(u1 == a && base + 1 <= b)
               + (int)(u2 == a && base + 2 <= b) + (int)(u3 == a && base + 3 <= b);
        }
    }
    #pragma unroll
    for (int o = 16; o > 0; o >>= 1) c += __shfl_xor_sync(0xffffffffu, c, o);
    if ((tid & 31) == 0) atomicAdd(&sm->red, c);
    __syncthreads();
    return sm->red;
}

// Exact selection: candidate i wins iff fewer than k candidates have a larger
// packed key. Keys are unique (index embedded), so exactly min(c,k) winners.
// Inner loop reads are warp-uniform -> smem broadcast (conflict-free).
__device__ void tk_rank_scatter(TKShared* sm, int c, int k, float* __restrict__ op, int tid) {
    for (int i = tid; i < c; i += TK_THREADS) {
        unsigned long long K = sm->cand[i];
        int r = 0;
        for (int j = 0; j < c; j++)
            r += (sm->cand[j] > K) ? 1 : 0;
        if (r < k) {
            unsigned u = (unsigned)(K >> 32);
            int idx = TK_D - 1 - (int)(K & 0xFFFFFFFFu);
            op[idx] = k2f(u);
        }
    }
}

__device__ __forceinline__ float tk_ladder(int i) {
    switch (i) {
        case 1: return 1.2f;
        case 2: return 0.0f;
        case 3: return -1.2f;
        case 4: return -2.8f;
        case 5: return -8.0f;
        default: return -3.0e38f;
    }
}

__global__ __launch_bounds__(TK_THREADS)
void TopKActivation_68324339745162_kernel(const float* __restrict__ in,
                                          const int* __restrict__ kptr,
                                          float* __restrict__ out) {
    __shared__ TKShared sm;
    const int tid = threadIdx.x;
    const size_t row = blockIdx.x;
    const float* rp = in + row * (size_t)TK_D;
    float*       op = out + row * (size_t)TK_D;

    int k = kptr ? *kptr : 64;
    if (k < 1) k = 1;
    if (k > TK_CAP) k = TK_CAP;

    if (tid == 0) sm.cnt = 0;
    __syncthreads();

    // ---- Pass 1 (the only pass on normal data): zero output + push x > 2.4 ----
    unsigned tk = f2k(2.4f);
    unsigned hi_k = 0xFFFFFFFFu;        // count(key > hi_k) == 0 < k, invariant
    tk_scan<true, false>(rp, op, tk, 0xFFFFFFFFu, &sm, tid);
    __syncthreads();
    int cnt = sm.cnt;

    // ---- Undershoot ladder (block-uniform; never taken for N(0,1) rows) ----
    int li = 0;
    while (cnt < k && li < 7) {
        unsigned tk_old = tk;
        li++;
        tk = (li < 7) ? f2k(tk_ladder(li)) : 0u;
        hi_k = tk_old;                  // count(key > tk_old) == cnt < k
        tk_scan<false, true>(rp, op, tk, tk_old, &sm, tid);
        __syncthreads();
        cnt = sm.cnt;
    }

    if (cnt <= TK_CAP) {                // fast path: exact rank selection
        tk_rank_scatter(&sm, cnt, k, op, tid);
        return;
    }

    // ---- Overflow slow path (pathological data only): key-space bisection ----
    // Invariants: count(key > lo) > CAP >= k ; count(key > hi_k) < k.
    unsigned lo = tk;
    while (hi_k - lo > 1u) {
        unsigned mid = lo + (hi_k - lo) / 2u;
        int cm = tk_count(rp, mid, 0, 0, &sm, tid);
        if (cm < k) {
            hi_k = mid;
        } else if (cm <= TK_CAP) {
            __syncthreads();
            if (tid == 0) sm.cnt = 0;
            __syncthreads();
            tk_scan<false, false>(rp, op, mid, 0xFFFFFFFFu, &sm, tid);
            __syncthreads();
            tk_rank_scatter(&sm, sm.cnt, k, op, tid);
            return;
        } else {
            lo = mid;
        }
    }

    // Massive-duplicate case: the k-th largest key is exactly hi_k.
    int cgt = tk_count(rp, hi_k, 0, 0, &sm, tid);   // strictly greater, < k
    int needed = k - cgt;

    // Scatter all strict winners (cgt < k <= CAP, so they all fit & all win).
    __syncthreads();
    if (tid == 0) sm.cnt = 0;
    __syncthreads();
    tk_scan<false, false>(rp, op, hi_k, 0xFFFFFFFFu, &sm, tid);
    __syncthreads();
    tk_rank_scatter(&sm, sm.cnt, k, op, tid);

    // Among keys == hi_k, take the `needed` smallest indices: bisect idx cutoff.
    int ilo = -1, ihi = TK_D - 1;
    while (ihi - ilo > 1) {
        int im = (ilo + ihi) / 2;
        int ce = tk_count(rp, hi_k, im, 1, &sm, tid);
        if (ce >= needed) ihi = im; else ilo = im;
    }
    __syncthreads();
    #pragma unroll
    for (int ch = 0; ch < TK_NCHUNK; ch++) {
        int base = ch * TK_CHUNK + tid * 4;
        float4 v = *(const float4*)(rp + base);
        if (f2k(v.x) == hi_k && base + 0 <= ihi) op[base + 0] = v.x;
        if (f2k(v.y) == hi_k && base + 1 <= ihi) op[base + 1] = v.y;
        if (f2k(v.z) == hi_k && base + 2 <= ihi) op[base + 2] = v.z;
        if (f2k(v.w) == hi_k && base + 3 <= ihi) op[base + 3] = v.w;
    }
}

extern "C" void kernel_launch(void* const* d_in, const int* in_sizes, int n_in,
                              void* d_out, int out_size) {
    const float* in = (const float*)d_in[0];
    const int*   kp = (n_in > 1) ? (const int*)d_in[1] : nullptr;
    int N = in_sizes[0] / TK_D;          // 8192 rows
    (void)out_size;
    TopKActivation_68324339745162_kernel<<<N, TK_THREADS>>>(in, kp, (float*)d_out);
}

// round 2
// speedup vs baseline: 1.9181x; 1.9181x over previous
#include <cuda_runtime.h>

#define TK_D       16384
#define TK_THREADS 256
#define TK_CHUNK   (TK_THREADS * 4)          // 1024 elements per iteration
#define TK_NITER   (TK_D / TK_CHUNK)         // 16
#define TK_CAP     1024

struct TKShared {
    unsigned long long cand[TK_CAP];   // (ordered_key << 32) | (D-1-idx)
    int cnt;
    int red;
};

// Order-preserving float->uint key: larger float <=> larger key.
__device__ __forceinline__ unsigned f2k(float f) {
    unsigned b = __float_as_uint(f);
    return b ^ ((unsigned)((int)b >> 31) | 0x80000000u);
}
__device__ __forceinline__ float k2f(unsigned u) {
    unsigned b = u ^ ((u & 0x80000000u) ? 0x80000000u : 0xFFFFFFFFu);
    return __uint_as_float(b);
}

__device__ __forceinline__ void tk_push(TKShared* sm, unsigned u, int idx) {
    int p = atomicAdd(&sm->cnt, 1);
    if (p < TK_CAP)
        sm->cand[p] = ((unsigned long long)u << 32) | (unsigned)(TK_D - 1 - idx);
}

// Hot-path scan: float window (tlo, thi]. Streams the row once with __ldcs
// (evict-first: input is read exactly once) and optionally writes the zero row.
template<bool ZERO_OUT, bool HAS_HI>
__device__ void tk_scanf(const float* __restrict__ rp, float* __restrict__ op,
                         float tlo, float thi, TKShared* sm, int tid) {
    #pragma unroll 4
    for (int c = 0; c < TK_NITER; c++) {
        int base = c * TK_CHUNK + tid * 4;
        float4 v = __ldcs((const float4*)(rp + base));
        if (ZERO_OUT)
            *(float4*)(op + base) = make_float4(0.f, 0.f, 0.f, 0.f);
        bool h0 = v.x > tlo, h1 = v.y > tlo, h2 = v.z > tlo, h3 = v.w > tlo;
        if (HAS_HI) {
            h0 = h0 && !(v.x > thi); h1 = h1 && !(v.y > thi);
            h2 = h2 && !(v.z > thi); h3 = h3 && !(v.w > thi);
        }
        if (h0 | h1 | h2 | h3) {              // ~1% taken on N(0,1) data
            if (h0) tk_push(sm, f2k(v.x), base + 0);
            if (h1) tk_push(sm, f2k(v.y), base + 1);
            if (h2) tk_push(sm, f2k(v.z), base + 2);
            if (h3) tk_push(sm, f2k(v.w), base + 3);
        }
    }
}

// Key-space scan: push keys in (klo, khi]. Fallback paths only.
__device__ void tk_scank(const float* __restrict__ rp,
                         unsigned klo, unsigned khi, TKShared* sm, int tid) {
    #pragma unroll 2
    for (int c = 0; c < TK_NITER; c++) {
        int base = c * TK_CHUNK + tid * 4;
        float4 v = __ldcs((const float4*)(rp + base));
        unsigned u0 = f2k(v.x), u1 = f2k(v.y), u2 = f2k(v.z), u3 = f2k(v.w);
        if (u0 > klo && u0 <= khi) tk_push(sm, u0, base + 0);
        if (u1 > klo && u1 <= khi) tk_push(sm, u1, base + 1);
        if (u2 > klo && u2 <= khi) tk_push(sm, u2, base + 2);
        if (u3 > klo && u3 <= khi) tk_push(sm, u3, base + 3);
    }
}

// mode 0: count keys > a ; mode 1: count (key == a && idx <= b). Block-wide.
__device__ int tk_count(const float* __restrict__ rp, unsigned a, int b, int mode,
                        TKShared* sm, int tid) {
    __syncthreads();
    if (tid == 0) sm->red = 0;
    __syncthreads();
    int c = 0;
    #pragma unroll 2
    for (int ch = 0; ch < TK_NITER; ch++) {
        int base = ch * TK_CHUNK + tid * 4;
        float4 v = __ldcs((const float4*)(rp + base));
        unsigned u0 = f2k(v.x), u1 = f2k(v.y), u2 = f2k(v.z), u3 = f2k(v.w);
        if (mode == 0) {
            c += (int)(u0 > a) + (int)(u1 > a) + (int)(u2 > a) + (int)(u3 > a);
        } else {
            c += (int)(u0 == a && base + 0 <= b) + (int)(u1 == a && base + 1 <= b)
               + (int)(u2 == a && base + 2 <= b) + (int)(u3 == a && base + 3 <= b);
        }
    }
    #pragma unroll
    for (int o = 16; o > 0; o >>= 1) c += __shfl_xor_sync(0xffffffffu, c, o);
    if ((tid & 31) == 0) atomicAdd(&sm->red, c);
    __syncthreads();
    return sm->red;
}

// Exact selection: candidate i wins iff fewer than k candidates have a larger
// packed key. Keys unique (index embedded) -> exactly min(c,k) winners.
// Inner reads are warp-uniform -> smem broadcast (conflict-free).
__device__ void tk_rank_scatter(TKShared* sm, int c, int k, float* __restrict__ op, int tid) {
    for (int i = tid; i < c; i += TK_THREADS) {
        unsigned long long K = sm->cand[i];
        int r = 0;
        for (int j = 0; j < c; j++)
            r += (sm->cand[j] > K) ? 1 : 0;
        if (r < k) {
            unsigned u = (unsigned)(K >> 32);
            int idx = TK_D - 1 - (int)(K & 0xFFFFFFFFu);
            op[idx] = k2f(u);
        }
    }
}

__global__ __launch_bounds__(TK_THREADS, 4)
void TopKActivation_68324339745162_kernel(const float* __restrict__ in,
                                          const int* __restrict__ kptr,
                                          float* __restrict__ out) {
    __shared__ TKShared sm;
    const int tid = threadIdx.x;
    const size_t row = blockIdx.x;
    const float* rp = in + row * (size_t)TK_D;
    float*       op = out + row * (size_t)TK_D;

    int k = kptr ? *kptr : 64;
    if (k < 1) k = 1;
    if (k > TK_CAP) k = TK_CAP;

    if (tid == 0) sm.cnt = 0;
    __syncthreads();

    // ---- Pass 1 (the only pass on normal data): zero output + push x > 2.4.
    // For iid N(0,1), E[count] = 16384 * P(x>2.4) ~= 134, sd ~= 11.6:
    // >=64 and <=1024 candidates at astronomic certainty.
    tk_scanf<true, false>(rp, op, 2.4f, 0.f, &sm, tid);
    __syncthreads();
    int cnt = sm.cnt;

    // ---- Undershoot ladder (block-uniform; not taken on N(0,1) data) ----
    unsigned lo_key = f2k(2.4f);
    unsigned hi_key = 0xFFFFFFFFu;      // count(key > hi_key) == 0 < k
    {
        float t_old = 2.4f;
        const float rungs[4] = {1.2f, 0.0f, -1.2f, -2.8f};
        int li = 0;
        while (cnt < k && li < 4) {
            float t_new = rungs[li];
            tk_scanf<false, true>(rp, op, t_new, t_old, &sm, tid);
            __syncthreads();
            cnt = sm.cnt;
            hi_key = f2k(t_old);
            lo_key = f2k(t_new);
            t_old = t_new;
            li++;
        }
        // key-space rungs cover the deep tail (-inf etc.)
        unsigned krungs[2] = {f2k(-8.0f), 0u};
        int ki = 0;
        while (cnt < k && ki < 2) {
            unsigned k_new = krungs[ki];
            tk_scank(rp, k_new, lo_key, &sm, tid);
            __syncthreads();
            cnt = sm.cnt;
            hi_key = lo_key;
            lo_key = k_new;
            ki++;
        }
    }

    if (cnt <= TK_CAP) {                // fast path: exact rank selection
        tk_rank_scatter(&sm, cnt, k, op, tid);
        return;
    }

    // ---- Overflow slow path (pathological data only): key-space bisection ----
    // Invariants: count(key > lo_key) >= cnt > CAP >= k ; count(key > hi_key) < k.
    unsigned lo = lo_key;
    while (hi_key - lo > 1u) {
        unsigned mid = lo + (hi_key - lo) / 2u;
        int cm = tk_count(rp, mid, 0, 0, &sm, tid);
        if (cm < k) {
            hi_key = mid;
        } else if (cm <= TK_CAP) {
            __syncthreads();
            if (tid == 0) sm.cnt = 0;
            __syncthreads();
            tk_scank(rp, mid, 0xFFFFFFFFu, &sm, tid);
            __syncthreads();
            tk_rank_scatter(&sm, sm.cnt, k, op, tid);
            return;
        } else {
            lo = mid;
        }
    }

    // Massive-duplicate case: the k-th largest key is exactly hi_key.
    int cgt = tk_count(rp, hi_key, 0, 0, &sm, tid);   // strictly greater, < k
    int needed = k - cgt;

    // Scatter all strict winners (cgt < k <= CAP: they all fit & all win).
    __syncthreads();
    if (tid == 0) sm.cnt = 0;
    __syncthreads();
    tk_scank(rp, hi_key, 0xFFFFFFFFu, &sm, tid);
    __syncthreads();
    tk_rank_scatter(&sm, sm.cnt, k, op, tid);

    // Among keys == hi_key, take the `needed` smallest indices: bisect cutoff.
    int ilo = -1, ihi = TK_D - 1;
    while (ihi - ilo > 1) {
        int im = (ilo + ihi) / 2;
        int ce = tk_count(rp, hi_key, im, 1, &sm, tid);
        if (ce >= needed) ihi = im; else ilo = im;
    }
    __syncthreads();
    #pragma unroll 2
    for (int ch = 0; ch < TK_NITER; ch++) {
        int base = ch * TK_CHUNK + tid * 4;
        float4 v = __ldcs((const float4*)(rp + base));
        if (f2k(v.x) == hi_key && base + 0 <= ihi) op[base + 0] = v.x;
        if (f2k(v.y) == hi_key && base + 1 <= ihi) op[base + 1] = v.y;
        if (f2k(v.z) == hi_key && base + 2 <= ihi) op[base + 2] = v.z;
        if (f2k(v.w) == hi_key && base + 3 <= ihi) op[base + 3] = v.w;
    }
}

extern "C" void kernel_launch(void* const* d_in, const int* in_sizes, int n_in,
                              void* d_out, int out_size) {
    const float* in = (const float*)d_in[0];
    const int*   kp = (n_in > 1) ? (const int*)d_in[1] : nullptr;
    int N = in_sizes[0] / TK_D;          // 8192 rows
    (void)out_size;
    TopKActivation_68324339745162_kernel<<<N, TK_THREADS>>>(in, kp, (float*)d_out);
}

// round 3
// speedup vs baseline: 2.0570x; 1.0724x over previous
#include <cuda_runtime.h>

#define TK_D       16384
#define TK_THREADS 256
#define TK_CHUNK   (TK_THREADS * 4)          // 1024 elements per iteration
#define TK_NITER   (TK_D / TK_CHUNK)         // 16
#define TK_CAP     512

struct TKShared {
    unsigned long long cand[TK_CAP];   // (ordered_key << 32) | (D-1-idx)
    int cnt;
    int red;
};

// Order-preserving float->uint key: larger float <=> larger key.
__device__ __forceinline__ unsigned f2k(float f) {
    unsigned b = __float_as_uint(f);
    return b ^ ((unsigned)((int)b >> 31) | 0x80000000u);
}
__device__ __forceinline__ float k2f(unsigned u) {
    unsigned b = u ^ ((u & 0x80000000u) ? 0x80000000u : 0xFFFFFFFFu);
    return __uint_as_float(b);
}

__device__ __forceinline__ void tk_push(TKShared* sm, unsigned u, int idx) {
    int p = atomicAdd(&sm->cnt, 1);
    if (p < TK_CAP)
        sm->cand[p] = ((unsigned long long)u << 32) | (unsigned)(TK_D - 1 - idx);
}

// Hot-path scan: float window (tlo, thi]. Streams the row once with __ldcs
// (evict-first: input read exactly once) and optionally writes the zero row.
// Unroll 8 front-batches 8 LDG.128 per warp -> high MLP.
template<bool ZERO_OUT, bool HAS_HI>
__device__ void tk_scanf(const float* __restrict__ rp, float* __restrict__ op,
                         float tlo, float thi, TKShared* sm, int tid) {
    #pragma unroll 8
    for (int c = 0; c < TK_NITER; c++) {
        int base = c * TK_CHUNK + tid * 4;
        float4 v = __ldcs((const float4*)(rp + base));
        if (ZERO_OUT)
            *(float4*)(op + base) = make_float4(0.f, 0.f, 0.f, 0.f);
        // One compare decides the (rare) branch: max of the quad vs threshold.
        float m = fmaxf(fmaxf(v.x, v.y), fmaxf(v.z, v.w));
        if (m > tlo) {                        // ~3% of quads on N(0,1) data
            bool h0 = v.x > tlo, h1 = v.y > tlo, h2 = v.z > tlo, h3 = v.w > tlo;
            if (HAS_HI) {
                h0 = h0 && !(v.x > thi); h1 = h1 && !(v.y > thi);
                h2 = h2 && !(v.z > thi); h3 = h3 && !(v.w > thi);
            }
            if (h0) tk_push(sm, f2k(v.x), base + 0);
            if (h1) tk_push(sm, f2k(v.y), base + 1);
            if (h2) tk_push(sm, f2k(v.z), base + 2);
            if (h3) tk_push(sm, f2k(v.w), base + 3);
        }
    }
}

// Key-space scan: push keys in (klo, khi]. Fallback paths only.
__device__ void tk_scank(const float* __restrict__ rp,
                         unsigned klo, unsigned khi, TKShared* sm, int tid) {
    #pragma unroll 2
    for (int c = 0; c < TK_NITER; c++) {
        int base = c * TK_CHUNK + tid * 4;
        float4 v = __ldcs((const float4*)(rp + base));
        unsigned u0 = f2k(v.x), u1 = f2k(v.y), u2 = f2k(v.z), u3 = f2k(v.w);
        if (u0 > klo && u0 <= khi) tk_push(sm, u0, base + 0);
        if (u1 > klo && u1 <= khi) tk_push(sm, u1, base + 1);
        if (u2 > klo && u2 <= khi) tk_push(sm, u2, base + 2);
        if (u3 > klo && u3 <= khi) tk_push(sm, u3, base + 3);
    }
}

// mode 0: count keys > a ; mode 1: count (key == a && idx <= b). Block-wide.
__device__ int tk_count(const float* __restrict__ rp, unsigned a, int b, int mode,
                        TKShared* sm, int tid) {
    __syncthreads();
    if (tid == 0) sm->red = 0;
    __syncthreads();
    int c = 0;
    #pragma unroll 2
    for (int ch = 0; ch < TK_NITER; ch++) {
        int base = ch * TK_CHUNK + tid * 4;
        float4 v = __ldcs((const float4*)(rp + base));
        unsigned u0 = f2k(v.x), u1 = f2k(v.y), u2 = f2k(v.z), u3 = f2k(v.w);
        if (mode == 0) {
            c += (int)(u0 > a) + (int)(u1 > a) + (int)(u2 > a) + (int)(u3 > a);
        } else {
            c += (int)(u0 == a && base + 0 <= b) + (int)(u1 == a && base + 1 <= b)
               + (int)(u2 == a && base + 2 <= b) + (int)(u3 == a && base + 3 <= b);
        }
    }
    #pragma unroll
    for (int o = 16; o > 0; o >>= 1) c += __shfl_xor_sync(0xffffffffu, c, o);
    if ((tid & 31) == 0) atomicAdd(&sm->red, c);
    __syncthreads();
    return sm->red;
}

// Exact selection: candidate i wins iff fewer than k candidates have a larger
// packed key. Keys unique (index embedded) -> exactly min(c,k) winners.
// Inner reads are warp-uniform -> smem broadcast (conflict-free).
__device__ void tk_rank_scatter(TKShared* sm, int c, int k, float* __restrict__ op, int tid) {
    for (int i = tid; i < c; i += TK_THREADS) {
        unsigned long long K = sm->cand[i];
        int r = 0;
        for (int j = 0; j < c; j++)
            r += (sm->cand[j] > K) ? 1 : 0;
        if (r < k) {
            unsigned u = (unsigned)(K >> 32);
            int idx = TK_D - 1 - (int)(K & 0xFFFFFFFFu);
            op[idx] = k2f(u);
        }
    }
}

__global__ __launch_bounds__(TK_THREADS, 6)
void TopKActivation_68324339745162_kernel(const float* __restrict__ in,
                                          const int* __restrict__ kptr,
                                          float* __restrict__ out) {
    __shared__ TKShared sm;
    const int tid = threadIdx.x;
    const size_t row = blockIdx.x;
    const float* rp = in + row * (size_t)TK_D;
    float*       op = out + row * (size_t)TK_D;

    int k = kptr ? *kptr : 64;
    if (k < 1) k = 1;
    if (k > TK_CAP) k = TK_CAP;

    if (tid == 0) sm.cnt = 0;
    __syncthreads();

    // ---- Pass 1 (the only pass on normal data): zero output + push x > 2.4.
    // For iid N(0,1), E[count] = 16384 * P(x>2.4) ~= 134, sd ~= 11.6:
    // >=64 and <=512 candidates at astronomic certainty (>20 sigma both sides).
    tk_scanf<true, false>(rp, op, 2.4f, 0.f, &sm, tid);
    __syncthreads();
    int cnt = sm.cnt;

    // ---- Undershoot ladder (block-uniform; not taken on N(0,1) data) ----
    unsigned lo_key = f2k(2.4f);
    unsigned hi_key = 0xFFFFFFFFu;      // count(key > hi_key) == 0 < k
    if (cnt < k || cnt > TK_CAP) {      // cold path wrapper
        float t_old = 2.4f;
        const float rungs[4] = {1.2f, 0.0f, -1.2f, -2.8f};
        int li = 0;
        while (cnt < k && li < 4) {
            float t_new = rungs[li];
            tk_scanf<false, true>(rp, op, t_new, t_old, &sm, tid);
            __syncthreads();
            cnt = sm.cnt;
            hi_key = f2k(t_old);
            lo_key = f2k(t_new);
            t_old = t_new;
            li++;
        }
        // key-space rungs cover the deep tail (-inf etc.)
        unsigned krungs[2] = {f2k(-8.0f), 0u};
        int ki = 0;
        while (cnt < k && ki < 2) {
            unsigned k_new = krungs[ki];
            tk_scank(rp, k_new, lo_key, &sm, tid);
            __syncthreads();
            cnt = sm.cnt;
            hi_key = lo_key;
            lo_key = k_new;
            ki++;
        }
    }

    if (cnt <= TK_CAP) {                // fast path: exact rank selection
        tk_rank_scatter(&sm, cnt, k, op, tid);
        return;
    }

    // ---- Overflow slow path (pathological data only): key-space bisection ----
    // Invariants: count(key > lo_key) >= cnt > CAP >= k ; count(key > hi_key) < k.
    unsigned lo = lo_key;
    while (hi_key - lo > 1u) {
        unsigned mid = lo + (hi_key - lo) / 2u;
        int cm = tk_count(rp, mid, 0, 0, &sm, tid);
        if (cm < k) {
            hi_key = mid;
        } else if (cm <= TK_CAP) {
            __syncthreads();
            if (tid == 0) sm.cnt = 0;
            __syncthreads();
            tk_scank(rp, mid, 0xFFFFFFFFu, &sm, tid);
            __syncthreads();
            tk_rank_scatter(&sm, sm.cnt, k, op, tid);
            return;
        } else {
            lo = mid;
        }
    }

    // Massive-duplicate case: the k-th largest key is exactly hi_key.
    int cgt = tk_count(rp, hi_key, 0, 0, &sm, tid);   // strictly greater, < k
    int needed = k - cgt;

    // Scatter all strict winners (cgt < k <= CAP: they all fit & all win).
    __syncthreads();
    if (tid == 0) sm.cnt = 0;
    __syncthreads();
    tk_scank(rp, hi_key, 0xFFFFFFFFu, &sm, tid);
    __syncthreads();
    tk_rank_scatter(&sm, sm.cnt, k, op, tid);

    // Among keys == hi_key, take the `needed` smallest indices: bisect cutoff.
    int ilo = -1, ihi = TK_D - 1;
    while (ihi - ilo > 1) {
        int im = (ilo + ihi) / 2;
        int ce = tk_count(rp, hi_key, im, 1, &sm, tid);
        if (ce >= needed) ihi = im; else ilo = im;
    }
    __syncthreads();
    #pragma unroll 2
    for (int ch = 0; ch < TK_NITER; ch++) {
        int base = ch * TK_CHUNK + tid * 4;
        float4 v = __ldcs((const float4*)(rp + base));
        if (f2k(v.x) == hi_key && base + 0 <= ihi) op[base + 0] = v.x;
        if (f2k(v.y) == hi_key && base + 1 <= ihi) op[base + 1] = v.y;
        if (f2k(v.z) == hi_key && base + 2 <= ihi) op[base + 2] = v.z;
        if (f2k(v.w) == hi_key && base + 3 <= ihi) op[base + 3] = v.w;
    }
}

extern "C" void kernel_launch(void* const* d_in, const int* in_sizes, int n_in,
                              void* d_out, int out_size) {
    const float* in = (const float*)d_in[0];
    const int*   kp = (n_in > 1) ? (const int*)d_in[1] : nullptr;
    int N = in_sizes[0] / TK_D;          // 8192 rows
    (void)out_size;
    TopKActivation_68324339745162_kernel<<<N, TK_THREADS>>>(in, kp, (float*)d_out);
}